// round 5
// baseline (speedup 1.0000x reference)
#include <cuda_runtime.h>
#include <cuda_bf16.h>
#include <cstdint>

// EdgeConvE: B=4, V=1024, C=64, E=16, K=32, OUT=128, NODES=4096, EDGES=131072
// src = repeat(arange(4096), 32) (structural) => segment n = edges [n*32,(n+1)*32)
// dst & 1023 = local neighbor (block-diagonal graphs).
//
// Algebra: feat@W = x_s@(W1-W2) + x_d@W2 + e@W3
//   A[n] = x_n@(W1-W2)+b ; C[n] = x_n@W2
//   out[n][j] = max(0, A[n][j] + max_k( C[dst_k][j] + e_k . W3[:,j] ))

#define NODES 4096
#define VDIM  1024
#define CDIM  64
#define EDIM  16
#define KNBR  32
#define OUTD  128
#define NPB   8      // nodes per block (edge kernel): 4 pipelined pairs

__device__ float g_A[NODES * OUTD];
__device__ float g_C[NODES * OUTD];

// ---------------- f32x2 helpers ----------------
__device__ __forceinline__ uint64_t pack_f32x2(float lo, float hi) {
    uint64_t r;
    asm("mov.b64 %0, {%1, %2};" : "=l"(r) : "f"(lo), "f"(hi));
    return r;
}
__device__ __forceinline__ void unpack_f32x2(float& lo, float& hi, uint64_t v) {
    asm("mov.b64 {%0, %1}, %2;" : "=f"(lo), "=f"(hi) : "l"(v));
}
__device__ __forceinline__ uint64_t fma_f32x2(uint64_t a, uint64_t b, uint64_t c) {
    uint64_t d;
    asm("fma.rn.f32x2 %0, %1, %2, %3;" : "=l"(d) : "l"(a), "l"(b), "l"(c));
    return d;
}
__device__ __forceinline__ void lds_v2_u64(uint64_t& a, uint64_t& b, uint32_t addr) {
    asm("ld.shared.v2.u64 {%0, %1}, [%2];" : "=l"(a), "=l"(b) : "r"(addr));
}
__device__ __forceinline__ uint64_t lds_u64(uint32_t addr) {
    uint64_t a;
    asm("ld.shared.u64 %0, [%1];" : "=l"(a) : "r"(addr));
    return a;
}
__device__ __forceinline__ uint32_t smem_u32(const void* p) {
    return (uint32_t)__cvta_generic_to_shared(p);
}
__device__ __forceinline__ void cp_async16(uint32_t s, const void* g) {
    asm volatile("cp.async.cg.shared.global [%0], [%1], 16;" :: "r"(s), "l"(g));
}

// ---------------------------------------------------------------------------
// Kernel 1: per-node linear tables (f32x2-packed over node pairs).
// NT_NODES=8 -> grid 512 for wave balance.
// ---------------------------------------------------------------------------
#define NT_NODES 8
__global__ void __launch_bounds__(128) node_tables_kernel(
    const float* __restrict__ x, const float* __restrict__ W,
    const float* __restrict__ bias)
{
    __shared__ float xs[CDIM][NT_NODES];
    const int j  = threadIdx.x;
    const int n0 = blockIdx.x * NT_NODES;

    for (int it = 0; it < NT_NODES * CDIM / 128; it++) {
        int idx = j + it * 128;
        xs[idx & 63][idx >> 6] = x[n0 * CDIM + idx];
    }
    __syncthreads();

    const float bj = bias[j];
    uint64_t accA[NT_NODES / 2], accC[NT_NODES / 2];
#pragma unroll
    for (int p = 0; p < NT_NODES / 2; p++) {
        accA[p] = pack_f32x2(bj, bj);
        accC[p] = pack_f32x2(0.0f, 0.0f);
    }
    const uint32_t xs_base = smem_u32(&xs[0][0]);

#pragma unroll 8
    for (int c = 0; c < CDIM; c++) {
        const float w1 = W[c * OUTD + j];
        const float w2 = W[(CDIM + c) * OUTD + j];
        const uint64_t wd2 = pack_f32x2(w1 - w2, w1 - w2);
        const uint64_t w22 = pack_f32x2(w2, w2);
        const uint32_t rowa = xs_base + c * (NT_NODES * 4);
#pragma unroll
        for (int p = 0; p < NT_NODES / 2; p++) {
            uint64_t xv2 = lds_u64(rowa + p * 8);
            accA[p] = fma_f32x2(xv2, wd2, accA[p]);
            accC[p] = fma_f32x2(xv2, w22, accC[p]);
        }
    }
#pragma unroll
    for (int p = 0; p < NT_NODES / 2; p++) {
        float a0, a1, c0, c1;
        unpack_f32x2(a0, a1, accA[p]);
        unpack_f32x2(c0, c1, accC[p]);
        g_A[(n0 + 2 * p) * OUTD + j]     = a0;
        g_A[(n0 + 2 * p + 1) * OUTD + j] = a1;
        g_C[(n0 + 2 * p) * OUTD + j]     = c0;
        g_C[(n0 + 2 * p + 1) * OUTD + j] = c1;
    }
}

// ---------------------------------------------------------------------------
// Kernel 2: 8 nodes/block, 4 pipelined pairs, all gathers issued upfront.
//   thread t: node = pair*2 + (t>>6), owns cols (2*(t&63), 2*(t&63)+1).
//   k-PAIR interleaved inner loop: 4 independent f32x2 FMA chains -> no
//   dependency stalls. C-table chunk prefetched one chunk ahead.
// ---------------------------------------------------------------------------
__global__ void __launch_bounds__(128) edge_max_kernel(
    const float* __restrict__ eattr,  // [4,1024,1024,16]
    const float* __restrict__ W,      // [144,128]
    const int*   __restrict__ dst,    // [131072]
    float*       __restrict__ out)    // [4096,128]
{
    const int t     = threadIdx.x;
    const int node0 = blockIdx.x * NPB;
    const int nn    = t >> 6;                  // node within pair
    const int l64   = t & 63;
    const int j0    = l64 * 2;

    __shared__ int sd[NPB * KNBR];                               // 256 ints
    __shared__ __align__(16) float se[NPB / 2][2][KNBR][EDIM];   // 16 KB

    // W3 t-pair columns for cols j0, j0+1 (registers, persist)
    uint64_t w3a[8], w3b[8];
#pragma unroll
    for (int p = 0; p < 8; p++) {
        w3a[p] = pack_f32x2(W[(2 * CDIM + 2 * p) * OUTD + j0],
                            W[(2 * CDIM + 2 * p + 1) * OUTD + j0]);
        w3b[p] = pack_f32x2(W[(2 * CDIM + 2 * p) * OUTD + j0 + 1],
                            W[(2 * CDIM + 2 * p + 1) * OUTD + j0 + 1]);
    }

    // ---- one coalesced dst load for all 8 nodes ----
    {
        int2 dd = reinterpret_cast<const int2*>(dst + node0 * KNBR)[t];
        sd[2 * t]     = dd.x;
        sd[2 * t + 1] = dd.y;
    }
    __syncthreads();

    // ---- issue all 4 gather groups upfront (deep pipeline) ----
#pragma unroll
    for (int p = 0; p < NPB / 2; p++) {
#pragma unroll
        for (int half = 0; half < 2; half++) {
            const int c  = t + half * 128;     // 256 chunks per pair
            const int cn = c >> 7;
            const int ck = (c >> 2) & 31;
            const int cq = c & 3;
            const int node = node0 + p * 2 + cn;
            const int ui = sd[(p * 2 + cn) * KNBR + ck] & (VDIM - 1);
            cp_async16(smem_u32(&se[p][cn][ck][cq * 4]),
                       eattr + ((size_t)node * VDIM + ui) * EDIM + cq * 4);
        }
        asm volatile("cp.async.commit_group;");
    }

#pragma unroll
    for (int p = 0; p < NPB / 2; p++) {
        if (p == 0)      asm volatile("cp.async.wait_group 3;");
        else if (p == 1) asm volatile("cp.async.wait_group 2;");
        else if (p == 2) asm volatile("cp.async.wait_group 1;");
        else             asm volatile("cp.async.wait_group 0;");
        __syncthreads();

        const int n = node0 + p * 2 + nn;
        const int* sdp = &sd[(p * 2 + nn) * KNBR];
        const uint32_t se_base = smem_u32(&se[p][nn][0][0]);

        float best0 = -1e30f, best1 = -1e30f;

        // preload C-table chunk 0 (8 rows, L2-resident)
        float2 cv[8];
#pragma unroll
        for (int u = 0; u < 8; u++)
            cv[u] = *reinterpret_cast<const float2*>(g_C + sdp[u] * OUTD + j0);

#pragma unroll
        for (int kb = 0; kb < KNBR; kb += 8) {
            // prefetch next chunk's C rows (overlaps with FMA below)
            float2 cvn[8];
            if (kb + 8 < KNBR) {
#pragma unroll
                for (int u = 0; u < 8; u++)
                    cvn[u] = *reinterpret_cast<const float2*>(
                                 g_C + sdp[kb + 8 + u] * OUTD + j0);
            }

#pragma unroll
            for (int u = 0; u < 8; u += 2) {
                const uint32_t r0 = se_base + (kb + u) * (EDIM * 4);
                const uint32_t r1 = r0 + EDIM * 4;
                uint64_t e0, e1, e2, e3, e4, e5, e6, e7;
                uint64_t f0, f1, f2, f3, f4, f5, f6, f7;
                lds_v2_u64(e0, e1, r0);       lds_v2_u64(f0, f1, r1);
                lds_v2_u64(e2, e3, r0 + 16);  lds_v2_u64(f2, f3, r1 + 16);
                lds_v2_u64(e4, e5, r0 + 32);  lds_v2_u64(f4, f5, r1 + 32);
                lds_v2_u64(e6, e7, r0 + 48);  lds_v2_u64(f6, f7, r1 + 48);

                // 4 independent chains: (col0,k) (col1,k) (col0,k+1) (col1,k+1)
                uint64_t a0 = pack_f32x2(cv[u].x, 0.0f);
                uint64_t a1 = pack_f32x2(cv[u].y, 0.0f);
                uint64_t b0 = pack_f32x2(cv[u + 1].x, 0.0f);
                uint64_t b1 = pack_f32x2(cv[u + 1].y, 0.0f);

                a0 = fma_f32x2(e0, w3a[0], a0);  a1 = fma_f32x2(e0, w3b[0], a1);
                b0 = fma_f32x2(f0, w3a[0], b0);  b1 = fma_f32x2(f0, w3b[0], b1);
                a0 = fma_f32x2(e1, w3a[1], a0);  a1 = fma_f32x2(e1, w3b[1], a1);
                b0 = fma_f32x2(f1, w3a[1], b0);  b1 = fma_f32x2(f1, w3b[1], b1);
                a0 = fma_f32x2(e2, w3a[2], a0);  a1 = fma_f32x2(e2, w3b[2], a1);
                b0 = fma_f32x2(f2, w3a[2], b0);  b1 = fma_f32x2(f2, w3b[2], b1);
                a0 = fma_f32x2(e3, w3a[3], a0);  a1 = fma_f32x2(e3, w3b[3], a1);
                b0 = fma_f32x2(f3, w3a[3], b0);  b1 = fma_f32x2(f3, w3b[3], b1);
                a0 = fma_f32x2(e4, w3a[4], a0);  a1 = fma_f32x2(e4, w3b[4], a1);
                b0 = fma_f32x2(f4, w3a[4], b0);  b1 = fma_f32x2(f4, w3b[4], b1);
                a0 = fma_f32x2(e5, w3a[5], a0);  a1 = fma_f32x2(e5, w3b[5], a1);
                b0 = fma_f32x2(f5, w3a[5], b0);  b1 = fma_f32x2(f5, w3b[5], b1);
                a0 = fma_f32x2(e6, w3a[6], a0);  a1 = fma_f32x2(e6, w3b[6], a1);
                b0 = fma_f32x2(f6, w3a[6], b0);  b1 = fma_f32x2(f6, w3b[6], b1);
                a0 = fma_f32x2(e7, w3a[7], a0);  a1 = fma_f32x2(e7, w3b[7], a1);
                b0 = fma_f32x2(f7, w3a[7], b0);  b1 = fma_f32x2(f7, w3b[7], b1);

                float lo, hi, lo2, hi2;
                unpack_f32x2(lo, hi, a0);
                unpack_f32x2(lo2, hi2, b0);
                best0 = fmaxf(best0, lo + hi);
                best0 = fmaxf(best0, lo2 + hi2);
                unpack_f32x2(lo, hi, a1);
                unpack_f32x2(lo2, hi2, b1);
                best1 = fmaxf(best1, lo + hi);
                best1 = fmaxf(best1, lo2 + hi2);
            }

#pragma unroll
            for (int u = 0; u < 8; u++) cv[u] = cvn[u];
        }

        const float2 av = *reinterpret_cast<const float2*>(g_A + n * OUTD + j0);
        float r0 = fmaxf(av.x + best0, 0.0f);
        float r1 = fmaxf(av.y + best1, 0.0f);
        *reinterpret_cast<float2*>(out + n * OUTD + j0) = make_float2(r0, r1);
    }
}

// ---------------------------------------------------------------------------
// Inputs: 0 node_features [4,1024,64] f32 | 1 edge_attributes [4,1024,1024,16] f32
//         2 W [144,128] f32 | 3 b [128] f32 | 4 src i32 (unused) | 5 dst i32
// Output: f32 [4,1024,128]
// ---------------------------------------------------------------------------
extern "C" void kernel_launch(void* const* d_in, const int* in_sizes, int n_in,
                              void* d_out, int out_size)
{
    const float* x     = (const float*)d_in[0];
    const float* eattr = (const float*)d_in[1];
    const float* W     = (const float*)d_in[2];
    const float* bias  = (const float*)d_in[3];
    const int*   dst   = (const int*)d_in[5];
    float*       out   = (float*)d_out;

    node_tables_kernel<<<NODES / NT_NODES, 128>>>(x, W, bias);
    edge_max_kernel<<<NODES / NPB, 128>>>(eattr, W, dst, out);
}

// round 6
// speedup vs baseline: 1.2098x; 1.2098x over previous
#include <cuda_runtime.h>
#include <cuda_bf16.h>
#include <cstdint>

// EdgeConvE: B=4, V=1024, C=64, E=16, K=32, OUT=128, NODES=4096, EDGES=131072
// src = repeat(arange(4096), 32) (structural) => segment n = edges [n*32,(n+1)*32)
// dst & 1023 = local neighbor (block-diagonal graphs).
//
// Algebra: feat@W = x_s@(W1-W2) + x_d@W2 + e@W3
//   A[n] = x_n@(W1-W2)+b ; C[n] = x_n@W2
//   out[n][j] = max(0, A[n][j] + max_k( C[dst_k][j] + e_k . W3[:,j] ))

#define NODES 4096
#define VDIM  1024
#define CDIM  64
#define EDIM  16
#define KNBR  32
#define OUTD  128
#define NPB   4      // nodes per block: 2 pipelined pairs (R3 structure)

__device__ float g_A[NODES * OUTD];
__device__ float g_C[NODES * OUTD];

// ---------------- f32x2 helpers ----------------
__device__ __forceinline__ uint64_t pack_f32x2(float lo, float hi) {
    uint64_t r;
    asm("mov.b64 %0, {%1, %2};" : "=l"(r) : "f"(lo), "f"(hi));
    return r;
}
__device__ __forceinline__ void unpack_f32x2(float& lo, float& hi, uint64_t v) {
    asm("mov.b64 {%0, %1}, %2;" : "=f"(lo), "=f"(hi) : "l"(v));
}
__device__ __forceinline__ uint64_t fma_f32x2(uint64_t a, uint64_t b, uint64_t c) {
    uint64_t d;
    asm("fma.rn.f32x2 %0, %1, %2, %3;" : "=l"(d) : "l"(a), "l"(b), "l"(c));
    return d;
}
__device__ __forceinline__ void lds_v2_u64(uint64_t& a, uint64_t& b, uint32_t addr) {
    asm("ld.shared.v2.u64 {%0, %1}, [%2];" : "=l"(a), "=l"(b) : "r"(addr));
}
__device__ __forceinline__ uint64_t lds_u64(uint32_t addr) {
    uint64_t a;
    asm("ld.shared.u64 %0, [%1];" : "=l"(a) : "r"(addr));
    return a;
}
__device__ __forceinline__ uint32_t smem_u32(const void* p) {
    return (uint32_t)__cvta_generic_to_shared(p);
}
__device__ __forceinline__ void cp_async16(uint32_t s, const void* g) {
    asm volatile("cp.async.cg.shared.global [%0], [%1], 16;" :: "r"(s), "l"(g));
}

// ---------------------------------------------------------------------------
// Kernel 1: per-node linear tables (f32x2-packed over node pairs). grid 512.
// ---------------------------------------------------------------------------
#define NT_NODES 8
__global__ void __launch_bounds__(128) node_tables_kernel(
    const float* __restrict__ x, const float* __restrict__ W,
    const float* __restrict__ bias)
{
    __shared__ float xs[CDIM][NT_NODES];
    const int j  = threadIdx.x;
    const int n0 = blockIdx.x * NT_NODES;

    for (int it = 0; it < NT_NODES * CDIM / 128; it++) {
        int idx = j + it * 128;
        xs[idx & 63][idx >> 6] = x[n0 * CDIM + idx];
    }
    __syncthreads();

    const float bj = bias[j];
    uint64_t accA[NT_NODES / 2], accC[NT_NODES / 2];
#pragma unroll
    for (int p = 0; p < NT_NODES / 2; p++) {
        accA[p] = pack_f32x2(bj, bj);
        accC[p] = pack_f32x2(0.0f, 0.0f);
    }
    const uint32_t xs_base = smem_u32(&xs[0][0]);

#pragma unroll 8
    for (int c = 0; c < CDIM; c++) {
        const float w1 = W[c * OUTD + j];
        const float w2 = W[(CDIM + c) * OUTD + j];
        const uint64_t wd2 = pack_f32x2(w1 - w2, w1 - w2);
        const uint64_t w22 = pack_f32x2(w2, w2);
        const uint32_t rowa = xs_base + c * (NT_NODES * 4);
#pragma unroll
        for (int p = 0; p < NT_NODES / 2; p++) {
            uint64_t xv2 = lds_u64(rowa + p * 8);
            accA[p] = fma_f32x2(xv2, wd2, accA[p]);
            accC[p] = fma_f32x2(xv2, w22, accC[p]);
        }
    }
#pragma unroll
    for (int p = 0; p < NT_NODES / 2; p++) {
        float a0, a1, c0, c1;
        unpack_f32x2(a0, a1, accA[p]);
        unpack_f32x2(c0, c1, accC[p]);
        g_A[(n0 + 2 * p) * OUTD + j]     = a0;
        g_A[(n0 + 2 * p + 1) * OUTD + j] = a1;
        g_C[(n0 + 2 * p) * OUTD + j]     = c0;
        g_C[(n0 + 2 * p + 1) * OUTD + j] = c1;
    }
}

// ---------------------------------------------------------------------------
// Kernel 2: 4 nodes/block in 2 pipelined pairs (grid 1024).
//   thread t: node = pair*2 + (t>>6), owns cols (2*(t&63), 2*(t&63)+1),
//   iterates all 32 k. C-table rows register-double-buffered one chunk
//   ahead so the ~250cyc L2 latency is exposed once per node, not per chunk.
// ---------------------------------------------------------------------------
__global__ void __launch_bounds__(128) edge_max_kernel(
    const float* __restrict__ eattr,  // [4,1024,1024,16]
    const float* __restrict__ W,      // [144,128]
    const int*   __restrict__ dst,    // [131072]
    float*       __restrict__ out)    // [4096,128]
{
    const int t     = threadIdx.x;
    const int node0 = blockIdx.x * NPB;
    const int nn    = t >> 6;                  // node within pair
    const int l64   = t & 63;
    const int j0    = l64 * 2;

    __shared__ int sd[NPB * KNBR];                           // 128 ints
    __shared__ __align__(16) float se[2][2][KNBR][EDIM];     // 8 KB

    // W3 t-pair columns for cols j0, j0+1 (registers, persist)
    uint64_t w3a[8], w3b[8];
#pragma unroll
    for (int p = 0; p < 8; p++) {
        w3a[p] = pack_f32x2(W[(2 * CDIM + 2 * p) * OUTD + j0],
                            W[(2 * CDIM + 2 * p + 1) * OUTD + j0]);
        w3b[p] = pack_f32x2(W[(2 * CDIM + 2 * p) * OUTD + j0 + 1],
                            W[(2 * CDIM + 2 * p + 1) * OUTD + j0 + 1]);
    }

    // ---- one coalesced dst load for all 4 nodes (1 int/thread) ----
    sd[t] = dst[node0 * KNBR + t];
    __syncthreads();

    // ---- issue both pairs' edge-attribute gathers upfront ----
#pragma unroll
    for (int p = 0; p < 2; p++) {
#pragma unroll
        for (int half = 0; half < 2; half++) {
            const int c  = t + half * 128;     // 256 chunks per pair
            const int cn = c >> 7;
            const int ck = (c >> 2) & 31;
            const int cq = c & 3;
            const int node = node0 + p * 2 + cn;
            const int ui = sd[(p * 2 + cn) * KNBR + ck] & (VDIM - 1);
            cp_async16(smem_u32(&se[p][cn][ck][cq * 4]),
                       eattr + ((size_t)node * VDIM + ui) * EDIM + cq * 4);
        }
        asm volatile("cp.async.commit_group;");
    }

#pragma unroll
    for (int p = 0; p < 2; p++) {
        if (p == 0) asm volatile("cp.async.wait_group 1;");
        else        asm volatile("cp.async.wait_group 0;");
        __syncthreads();

        const int n = node0 + p * 2 + nn;
        const int* sdp = &sd[(p * 2 + nn) * KNBR];
        const uint32_t se_base = smem_u32(&se[p][nn][0][0]);

        float best0 = -1e30f, best1 = -1e30f;

        // preload C-table chunk 0 (L2-resident)
        float2 cv[8];
#pragma unroll
        for (int u = 0; u < 8; u++)
            cv[u] = *reinterpret_cast<const float2*>(g_C + sdp[u] * OUTD + j0);

#pragma unroll
        for (int kb = 0; kb < KNBR; kb += 8) {
            // prefetch next chunk's C rows: overlaps with this chunk's FMA
            float2 cvn[8];
            if (kb + 8 < KNBR) {
#pragma unroll
                for (int u = 0; u < 8; u++)
                    cvn[u] = *reinterpret_cast<const float2*>(
                                 g_C + sdp[kb + 8 + u] * OUTD + j0);
            }

#pragma unroll
            for (int u = 0; u < 8; u++) {
                const uint32_t row = se_base + (kb + u) * (EDIM * 4);
                uint64_t e0, e1, e2, e3, e4, e5, e6, e7;
                lds_v2_u64(e0, e1, row);
                lds_v2_u64(e2, e3, row + 16);
                lds_v2_u64(e4, e5, row + 32);
                lds_v2_u64(e6, e7, row + 48);

                uint64_t a0 = pack_f32x2(cv[u].x, 0.0f);
                uint64_t a1 = pack_f32x2(cv[u].y, 0.0f);
                a0 = fma_f32x2(e0, w3a[0], a0);  a1 = fma_f32x2(e0, w3b[0], a1);
                a0 = fma_f32x2(e1, w3a[1], a0);  a1 = fma_f32x2(e1, w3b[1], a1);
                a0 = fma_f32x2(e2, w3a[2], a0);  a1 = fma_f32x2(e2, w3b[2], a1);
                a0 = fma_f32x2(e3, w3a[3], a0);  a1 = fma_f32x2(e3, w3b[3], a1);
                a0 = fma_f32x2(e4, w3a[4], a0);  a1 = fma_f32x2(e4, w3b[4], a1);
                a0 = fma_f32x2(e5, w3a[5], a0);  a1 = fma_f32x2(e5, w3b[5], a1);
                a0 = fma_f32x2(e6, w3a[6], a0);  a1 = fma_f32x2(e6, w3b[6], a1);
                a0 = fma_f32x2(e7, w3a[7], a0);  a1 = fma_f32x2(e7, w3b[7], a1);

                float lo0, hi0, lo1, hi1;
                unpack_f32x2(lo0, hi0, a0);
                unpack_f32x2(lo1, hi1, a1);
                best0 = fmaxf(best0, lo0 + hi0);
                best1 = fmaxf(best1, lo1 + hi1);
            }

#pragma unroll
            for (int u = 0; u < 8; u++) cv[u] = cvn[u];
        }

        const float2 av = *reinterpret_cast<const float2*>(g_A + n * OUTD + j0);
        float r0 = fmaxf(av.x + best0, 0.0f);
        float r1 = fmaxf(av.y + best1, 0.0f);
        *reinterpret_cast<float2*>(out + n * OUTD + j0) = make_float2(r0, r1);
    }
}

// ---------------------------------------------------------------------------
// Inputs: 0 node_features [4,1024,64] f32 | 1 edge_attributes [4,1024,1024,16] f32
//         2 W [144,128] f32 | 3 b [128] f32 | 4 src i32 (unused) | 5 dst i32
// Output: f32 [4,1024,128]
// ---------------------------------------------------------------------------
extern "C" void kernel_launch(void* const* d_in, const int* in_sizes, int n_in,
                              void* d_out, int out_size)
{
    const float* x     = (const float*)d_in[0];
    const float* eattr = (const float*)d_in[1];
    const float* W     = (const float*)d_in[2];
    const float* bias  = (const float*)d_in[3];
    const int*   dst   = (const int*)d_in[5];
    float*       out   = (float*)d_out;

    node_tables_kernel<<<NODES / NT_NODES, 128>>>(x, W, bias);
    edge_max_kernel<<<NODES / NPB, 128>>>(eattr, W, dst, out);
}